// round 14
// baseline (speedup 1.0000x reference)
#include <cuda_runtime.h>
#include <cuda_fp16.h>
#include <stdint.h>
#include <math.h>

#define BB   256
#define NT   196
#define NP   208              // NT padded to 13*16
#define DIM  384
#define HH   12
#define KD   32
#define VD   32
#define MM   (BB*NT)          // 50176
#define FF   (HH*(2*KD+VD))   // 1152
#define QK_SCALE 0.17677669529663687f  // 32^-0.5

typedef unsigned short u16;

// ---------------- scratch (static device arrays; no cudaMalloc) ---------------
__device__ u16   g_xn16 [MM*DIM];        // LN output, fp16
__device__ u16   g_q16  [BB*HH*NT*KD];   // q*scale, fp16
__device__ u16   g_k16  [BB*HH*NT*KD];
__device__ u16   g_v16  [BB*HH*NT*VD];
__device__ u16   g_att16[MM*DIM];        // attention out, fp16
__device__ u16   g_b16  [HH*NP*NP];      // expanded bias fp16, pad = -inf
__device__ u16   g_qkvw16 [FF*DIM];      // weights, fp16
__device__ u16   g_projw16[DIM*DIM];

// ---------------- helpers -----------------------------------------------------
__device__ __forceinline__ uint32_t pack2(float lo, float hi) {
    half2 h = __floats2half2_rn(lo, hi);
    return *(uint32_t*)&h;
}
__device__ __forceinline__ void mma_f16(float* c, const uint32_t* a, const uint32_t* b) {
    asm volatile(
        "mma.sync.aligned.m16n8k16.row.col.f32.f16.f16.f32 "
        "{%0,%1,%2,%3}, {%4,%5,%6,%7}, {%8,%9}, {%0,%1,%2,%3};"
        : "+f"(c[0]), "+f"(c[1]), "+f"(c[2]), "+f"(c[3])
        : "r"(a[0]), "r"(a[1]), "r"(a[2]), "r"(a[3]), "r"(b[0]), "r"(b[1]));
}
__device__ __forceinline__ void cp_async16(uint32_t saddr, const void* gptr) {
    asm volatile("cp.async.ca.shared.global [%0], [%1], 16;\n" :: "r"(saddr), "l"(gptr));
}
__device__ __forceinline__ void ldsm_x4(uint32_t* r, uint32_t saddr) {
    asm volatile("ldmatrix.sync.aligned.m8n8.x4.shared.b16 {%0,%1,%2,%3}, [%4];"
        : "=r"(r[0]), "=r"(r[1]), "=r"(r[2]), "=r"(r[3]) : "r"(saddr));
}

// ---------------- kernel 0: convert both weight matrices to fp16 --------------
__global__ void cvt_f16_kernel(const float* __restrict__ in1, u16* __restrict__ out1, int n1_4,
                               const float* __restrict__ in2, u16* __restrict__ out2, int n2_4) {
    int i = blockIdx.x * 256 + threadIdx.x;
    if (i < n1_4) {
        float4 v = *(const float4*)(in1 + i*4);
        uint2 o;
        o.x = pack2(v.x, v.y);
        o.y = pack2(v.z, v.w);
        *(uint2*)(out1 + i*4) = o;
    }
    int j = i - n1_4;
    if (j >= 0 && j < n2_4) {
        float4 v = *(const float4*)(in2 + j*4);
        uint2 o;
        o.x = pack2(v.x, v.y);
        o.y = pack2(v.z, v.w);
        *(uint2*)(out2 + j*4) = o;
    }
}

// ---------------- kernel 1: LayerNorm -> fp16 ---------------------------------
__global__ void __launch_bounds__(256) ln_kernel(const float* __restrict__ x,
                                                 const float* __restrict__ w,
                                                 const float* __restrict__ b) {
    int row  = blockIdx.x * 8 + (threadIdx.x >> 5);
    int lane = threadIdx.x & 31;
    const float* xr = x + (size_t)row * DIM;
    float4 v[3];
    float sum = 0.f, sq = 0.f;
#pragma unroll
    for (int j = 0; j < 3; j++) {
        v[j] = *(const float4*)(xr + j*128 + lane*4);
        sum += v[j].x + v[j].y + v[j].z + v[j].w;
        sq  += v[j].x*v[j].x + v[j].y*v[j].y + v[j].z*v[j].z + v[j].w*v[j].w;
    }
#pragma unroll
    for (int o = 16; o; o >>= 1) {
        sum += __shfl_xor_sync(0xffffffffu, sum, o);
        sq  += __shfl_xor_sync(0xffffffffu, sq,  o);
    }
    float mean = sum * (1.f/DIM);
    float var  = sq  * (1.f/DIM) - mean*mean;
    float inv  = rsqrtf(var + 1e-5f);
    u16* orow = g_xn16 + (size_t)row * DIM;
#pragma unroll
    for (int j = 0; j < 3; j++) {
        float4 ww = *(const float4*)(w + j*128 + lane*4);
        float4 bb = *(const float4*)(b + j*128 + lane*4);
        uint2 o4;
        o4.x = pack2((v[j].x - mean)*inv*ww.x + bb.x, (v[j].y - mean)*inv*ww.y + bb.y);
        o4.y = pack2((v[j].z - mean)*inv*ww.z + bb.z, (v[j].w - mean)*inv*ww.w + bb.w);
        *(uint2*)(orow + j*128 + lane*4) = o4;
    }
}

// ---------------- bias expansion: gb16[h][n][m], fp16 -------------------------
__global__ void bias_expand(const float* __restrict__ ab, const int* __restrict__ bidx) {
    int n = blockIdx.x, h = blockIdx.y, m = threadIdx.x;
    float v = -1e30f;                              // -> -inf in fp16 -> exp = 0
    if (n < NT && m < NT) v = ab[h*NT + bidx[n*NT + m]];
    half hv = __float2half_rn(v);
    g_b16[((size_t)h*NP + n)*NP + m] = *(u16*)&hv;
}

// ---------------- kernel 2/4: FP16 GEMM, 128x128, k-slab 32, 4-stage ----------
// Stage: A[128 rows][80B] + B[128][80B] = 20KB; 4 stages = 80KB -> 2 blocks/SM.
// Pitch 20 half2 (80B): 16B-aligned rows for LDSM, 20r mod 32 conflict-free.
// 3 slabs in flight; ONE wait_group + ONE __syncthreads per slab.
#define GPITCH 20            // half2 per row
#define GSTG_B 20480         // bytes per stage (A 10240 + B 10240)
template<bool QKV>
__global__ void __launch_bounds__(256) gemm_f16(const u16* __restrict__ W,
                                                const float* __restrict__ bias,
                                                float* __restrict__ C) {
    extern __shared__ uint32_t sm[];
    const u16* A = QKV ? g_xn16 : g_att16;

    int tid  = threadIdx.x;
    int wid  = tid >> 5, lane = tid & 31;
    int g = lane >> 2, t = lane & 3;
    int warp_m = (wid >> 1) * 32;   // 0,32,64,96
    int warp_n = (wid & 1) * 64;    // 0,64
    int col0 = blockIdx.x * 128;
    int row0 = blockIdx.y * 128;

    int lr = tid >> 2;              // 0..63 (row; also +64)
    int lc = tid & 3;               // 16B chunk in 64B row
    uint32_t sb = (uint32_t)__cvta_generic_to_shared(sm);

    // ldmatrix lane address components (half2 units)
    int a_row = warp_m + (lane & 15);                       // + mt*16
    int a_off = (lane >> 4) * 4;                            // + kc*8
    int b_row = warp_n + ((lane & 7) | ((lane >> 4) << 3)); // + p*16
    int b_off = ((lane >> 3) & 1) * 4;                      // + kc*8

    float acc[2][8][4];
#pragma unroll
    for (int i = 0; i < 2; i++)
#pragma unroll
        for (int j = 0; j < 8; j++)
#pragma unroll
            for (int k = 0; k < 4; k++) acc[i][j][k] = 0.f;

    auto load_stage = [&](int st, int kt) {
        uint32_t baseA = sb + st*GSTG_B;
        uint32_t baseB = baseA + 10240;
#pragma unroll
        for (int it = 0; it < 2; it++) {
            int r = lr + it*64;
            cp_async16(baseA + r*80 + lc*16,
                       A + (size_t)(row0 + r)*DIM + kt*32 + lc*8);
            cp_async16(baseB + r*80 + lc*16,
                       W + (size_t)(col0 + r)*DIM + kt*32 + lc*8);
        }
        asm volatile("cp.async.commit_group;\n" ::);
    };

    const int T = DIM / 32;         // 12
    load_stage(0, 0);
    load_stage(1, 1);
    load_stage(2, 2);

    for (int tt = 0; tt < T; tt++) {
        // ensure stage tt is complete (clamp wait depth at the tail)
        if (tt + 2 < T)       asm volatile("cp.async.wait_group 2;\n" ::);
        else if (tt + 1 < T)  asm volatile("cp.async.wait_group 1;\n" ::);
        else                  asm volatile("cp.async.wait_group 0;\n" ::);
        __syncthreads();      // publish stage tt; retire reads of stage tt-1

        if (tt + 3 < T) load_stage((tt+3)&3, tt+3);

        uint32_t sbA = sb + (tt&3)*GSTG_B;
        uint32_t sbB = sbA + 10240;
#pragma unroll
        for (int kc = 0; kc < 2; kc++) {          // 2 x k16 chunks in 32-k slab
            uint32_t af[2][4], bf[8][2];
#pragma unroll
            for (int mt = 0; mt < 2; mt++)
                ldsm_x4(af[mt], sbA + ((a_row + mt*16)*GPITCH + kc*8 + a_off)*4);
#pragma unroll
            for (int p = 0; p < 4; p++) {
                uint32_t r4[4];
                ldsm_x4(r4, sbB + ((b_row + p*16)*GPITCH + kc*8 + b_off)*4);
                bf[2*p  ][0] = r4[0]; bf[2*p  ][1] = r4[1];
                bf[2*p+1][0] = r4[2]; bf[2*p+1][1] = r4[3];
            }
#pragma unroll
            for (int mt = 0; mt < 2; mt++)
#pragma unroll
                for (int nt = 0; nt < 8; nt++)
                    mma_f16(acc[mt][nt], af[mt], bf[nt]);
        }
    }

#pragma unroll
    for (int mt = 0; mt < 2; mt++) {
#pragma unroll
        for (int nt = 0; nt < 8; nt++) {
            int nn0 = col0 + warp_n + nt*8 + 2*t;
#pragma unroll
            for (int rr = 0; rr < 2; rr++) {
                int m = row0 + warp_m + mt*16 + g + rr*8;
                float v0 = acc[mt][nt][rr*2+0] + bias[nn0];
                float v1 = acc[mt][nt][rr*2+1] + bias[nn0+1];
                if (QKV) {
                    int h  = nn0 / 96, cm = nn0 - h*96;
                    int seg = cm >> 5, c = cm & 31;
                    if (seg == 0) { v0 *= QK_SCALE; v1 *= QK_SCALE; }
                    int b_ = m / NT, n_ = m - b_*NT;
                    u16* dst = (seg == 0 ? g_q16 : (seg == 1 ? g_k16 : g_v16))
                               + ((size_t)(b_*HH + h)*NT + n_)*32 + c;
                    *(uint32_t*)dst = pack2(v0, v1);
                } else {
                    float2 o2 = {v0, v1};
                    *(float2*)(C + (size_t)m*DIM + nn0) = o2;
                }
            }
        }
    }
}

// ---------------- kernel 3: fp16 flash attention (no-max softmax) -------------
// UNCHANGED from round 11 (known good).
#define KP2 20
#define VP2 108
template<int NTC>
__device__ __forceinline__ void attn_chunk(int cb, const uint32_t qa[2][4],
                                           const u16* gb0, const u16* gb1,
                                           const uint32_t* Ksh, const uint32_t* Vt,
                                           int lane, float& l0, float& l1, float o[4][4]) {
    int g = lane >> 2, t = lane & 3;
    float s[NTC][4];
#pragma unroll
    for (int nt = 0; nt < NTC; nt++) { s[nt][0]=0.f; s[nt][1]=0.f; s[nt][2]=0.f; s[nt][3]=0.f; }
#pragma unroll
    for (int nt = 0; nt < NTC; nt++) {
        int m = cb + nt*8 + g;
#pragma unroll
        for (int kc = 0; kc < 2; kc++) {
            uint32_t bfr[2];
            bfr[0] = Ksh[m*KP2 + kc*8 + t];
            bfr[1] = Ksh[m*KP2 + kc*8 + t + 4];
            mma_f16(s[nt], qa[kc], bfr);
        }
    }
#pragma unroll
    for (int nt = 0; nt < NTC; nt++) {
        int cc = cb + nt*8 + 2*t;
        float2 b0 = __half22float2(*(const half2*)(gb0 + cc));
        float2 b1 = __half22float2(*(const half2*)(gb1 + cc));
        s[nt][0] = __expf(s[nt][0] + b0.x); l0 += s[nt][0];
        s[nt][1] = __expf(s[nt][1] + b0.y); l0 += s[nt][1];
        s[nt][2] = __expf(s[nt][2] + b1.x); l1 += s[nt][2];
        s[nt][3] = __expf(s[nt][3] + b1.y); l1 += s[nt][3];
    }
    // O += P V : P C-frag (c0,c1)=(tok 2t,2t+1) maps directly to fp16 A-frag
#pragma unroll
    for (int gi = 0; gi < NTC/2; gi++) {
        uint32_t pa[4];
        pa[0] = pack2(s[2*gi  ][0], s[2*gi  ][1]);
        pa[1] = pack2(s[2*gi  ][2], s[2*gi  ][3]);
        pa[2] = pack2(s[2*gi+1][0], s[2*gi+1][1]);
        pa[3] = pack2(s[2*gi+1][2], s[2*gi+1][3]);
        int jb = cb/2 + gi*8 + t;
#pragma unroll
        for (int vt = 0; vt < 4; vt++) {
            int d = vt*8 + g;
            uint32_t bfr[2];
            bfr[0] = Vt[d*VP2 + jb];
            bfr[1] = Vt[d*VP2 + jb + 4];
            mma_f16(o[vt], pa, bfr);
        }
    }
}

__global__ void __launch_bounds__(224, 2) attn_mma() {
    extern __shared__ uint32_t smu[];
    uint32_t* Ksh = smu;                 // [208][20] half2
    uint32_t* Vt  = smu + NP*KP2;        // [32][108] half2, (tok even, tok odd)

    int bh = blockIdx.x;
    int b_ = bh / HH;
    int h  = bh - b_*HH;
    int tid = threadIdx.x, w = tid >> 5, lane = tid & 31;
    int g = lane >> 2, t = lane & 3;

    for (int i = tid; i < NP*4; i += 224) {
        int m = i >> 2, c4 = i & 3;
        uint4 kv = {0u,0u,0u,0u};
        if (m < NT) kv = *(const uint4*)(g_k16 + ((size_t)bh*NT + m)*KD + c4*8);
        *(uint4*)&Ksh[m*KP2 + c4*4] = kv;
    }
    for (int i = tid; i < 104*16; i += 224) {
        int j = i >> 4, d2 = i & 15;
        uint32_t va = 0u, vb = 0u;
        if (2*j < NT) {
            va = *(const uint32_t*)(g_v16 + ((size_t)bh*NT + 2*j  )*VD + d2*2);
            vb = *(const uint32_t*)(g_v16 + ((size_t)bh*NT + 2*j+1)*VD + d2*2);
        }
        half2 ha = *(half2*)&va, hb = *(half2*)&vb;
        half2 lo = __halves2half2(__low2half(ha),  __low2half(hb));
        half2 hi = __halves2half2(__high2half(ha), __high2half(hb));
        Vt[(2*d2  )*VP2 + j] = *(uint32_t*)&lo;
        Vt[(2*d2+1)*VP2 + j] = *(uint32_t*)&hi;
    }
    __syncthreads();

    for (int iter = 0; iter < 2; iter++) {
        int tile = w + iter*7;
        if (tile >= 13) break;
        int r0 = tile*16 + g;
        int r1 = r0 + 8;

        uint32_t qa[2][4];
        const u16* q0p = g_q16 + ((size_t)bh*NT + r0)*KD;
        const u16* q1p = g_q16 + ((size_t)bh*NT + r1)*KD;
#pragma unroll
        for (int kc = 0; kc < 2; kc++) {
            qa[kc][0] = (r0 < NT) ? *(const uint32_t*)(q0p + (kc*8 + t)*2)     : 0u;
            qa[kc][1] = (r1 < NT) ? *(const uint32_t*)(q1p + (kc*8 + t)*2)     : 0u;
            qa[kc][2] = (r0 < NT) ? *(const uint32_t*)(q0p + (kc*8 + t + 4)*2) : 0u;
            qa[kc][3] = (r1 < NT) ? *(const uint32_t*)(q1p + (kc*8 + t + 4)*2) : 0u;
        }

        const u16* gb0 = g_b16 + ((size_t)h*NP + r0)*NP;
        const u16* gb1 = g_b16 + ((size_t)h*NP + r1)*NP;

        float l0 = 0.f, l1 = 0.f;
        float o[4][4];
#pragma unroll
        for (int vt = 0; vt < 4; vt++) { o[vt][0]=0.f; o[vt][1]=0.f; o[vt][2]=0.f; o[vt][3]=0.f; }

        attn_chunk<14>(0,   qa, gb0, gb1, Ksh, Vt, lane, l0, l1, o);   // cols 0..111
        attn_chunk<12>(112, qa, gb0, gb1, Ksh, Vt, lane, l0, l1, o);   // cols 112..207

        l0 += __shfl_xor_sync(0xffffffffu, l0, 1);
        l0 += __shfl_xor_sync(0xffffffffu, l0, 2);
        l1 += __shfl_xor_sync(0xffffffffu, l1, 1);
        l1 += __shfl_xor_sync(0xffffffffu, l1, 2);
        float inv0 = __fdividef(1.f, l0);
        float inv1 = __fdividef(1.f, l1);

        if (r0 < NT) {
            u16* orow = g_att16 + ((size_t)(b_*NT + r0))*DIM + h*VD;
#pragma unroll
            for (int vt = 0; vt < 4; vt++)
                *(uint32_t*)(orow + vt*8 + 2*t) = pack2(o[vt][0]*inv0, o[vt][1]*inv0);
        }
        if (r1 < NT) {
            u16* orow = g_att16 + ((size_t)(b_*NT + r1))*DIM + h*VD;
#pragma unroll
            for (int vt = 0; vt < 4; vt++)
                *(uint32_t*)(orow + vt*8 + 2*t) = pack2(o[vt][2]*inv1, o[vt][3]*inv1);
        }
    }
}

// ---------------- launch ------------------------------------------------------
extern "C" void kernel_launch(void* const* d_in, const int* in_sizes, int n_in,
                              void* d_out, int out_size) {
    const float* x      = (const float*)d_in[0];
    const float* norm_w = (const float*)d_in[1];
    const float* norm_b = (const float*)d_in[2];
    const float* qkv_w  = (const float*)d_in[3];
    const float* qkv_b  = (const float*)d_in[4];
    const float* attb   = (const float*)d_in[5];
    const float* proj_w = (const float*)d_in[6];
    const float* proj_b = (const float*)d_in[7];
    const int*   bidx   = (const int*)  d_in[8];
    float* out = (float*)d_out;

    u16* qkvw16;  cudaGetSymbolAddress((void**)&qkvw16,  g_qkvw16);
    u16* projw16; cudaGetSymbolAddress((void**)&projw16, g_projw16);

    const int gemm_smem = 4 * GSTG_B;                                     // 81920
    const int attn_smem = (NP*KP2 + 32*VP2) * (int)sizeof(uint32_t);      // 30464
    cudaFuncSetAttribute(gemm_f16<true >, cudaFuncAttributeMaxDynamicSharedMemorySize, gemm_smem);
    cudaFuncSetAttribute(gemm_f16<false>, cudaFuncAttributeMaxDynamicSharedMemorySize, gemm_smem);
    cudaFuncSetAttribute(attn_mma,        cudaFuncAttributeMaxDynamicSharedMemorySize, attn_smem);

    const int ncvt = FF*DIM/4 + DIM*DIM/4;
    cvt_f16_kernel<<<(ncvt + 255)/256, 256>>>(qkv_w, qkvw16, FF*DIM/4,
                                              proj_w, projw16, DIM*DIM/4);
    ln_kernel<<<MM/8, 256>>>(x, norm_w, norm_b);
    bias_expand<<<dim3(NP, HH), NP>>>(attb, bidx);
    gemm_f16<true ><<<dim3(FF/128,  MM/128), 256, gemm_smem>>>(qkvw16, qkv_b, nullptr);
    attn_mma<<<BB*HH, 224, attn_smem>>>();
    gemm_f16<false><<<dim3(DIM/128, MM/128), 256, gemm_smem>>>(projw16, proj_b, out);
}

// round 15
// speedup vs baseline: 1.0951x; 1.0951x over previous
#include <cuda_runtime.h>
#include <cuda_fp16.h>
#include <stdint.h>
#include <math.h>

#define BB   256
#define NT   196
#define NP   208              // NT padded to 13*16
#define DIM  384
#define HH   12
#define KD   32
#define VD   32
#define MM   (BB*NT)          // 50176
#define FF   (HH*(2*KD+VD))   // 1152
#define QK_SCALE 0.17677669529663687f  // 32^-0.5
#define LOG2E    1.4426950408889634f

typedef unsigned short u16;

// ---------------- scratch (static device arrays; no cudaMalloc) ---------------
__device__ u16   g_xn16 [MM*DIM];        // LN output, fp16
__device__ u16   g_q16  [BB*HH*NT*KD];   // q*scale*log2e, fp16
__device__ u16   g_k16  [BB*HH*NT*KD];
__device__ u16   g_v16  [BB*HH*NT*VD];
__device__ u16   g_att16[MM*DIM];        // attention out, fp16
__device__ u16   g_b16  [HH*NP*NP];      // expanded bias*log2e fp16, pad = -inf
__device__ u16   g_qkvw16 [FF*DIM];      // weights, fp16
__device__ u16   g_projw16[DIM*DIM];

// ---------------- helpers -----------------------------------------------------
__device__ __forceinline__ uint32_t pack2(float lo, float hi) {
    half2 h = __floats2half2_rn(lo, hi);
    return *(uint32_t*)&h;
}
__device__ __forceinline__ float ex2(float x) {
    float r;
    asm("ex2.approx.f32 %0, %1;" : "=f"(r) : "f"(x));
    return r;
}
__device__ __forceinline__ void mma_f16(float* c, const uint32_t* a, const uint32_t* b) {
    asm volatile(
        "mma.sync.aligned.m16n8k16.row.col.f32.f16.f16.f32 "
        "{%0,%1,%2,%3}, {%4,%5,%6,%7}, {%8,%9}, {%0,%1,%2,%3};"
        : "+f"(c[0]), "+f"(c[1]), "+f"(c[2]), "+f"(c[3])
        : "r"(a[0]), "r"(a[1]), "r"(a[2]), "r"(a[3]), "r"(b[0]), "r"(b[1]));
}
__device__ __forceinline__ void cp_async16(uint32_t saddr, const void* gptr) {
    asm volatile("cp.async.ca.shared.global [%0], [%1], 16;\n" :: "r"(saddr), "l"(gptr));
}
__device__ __forceinline__ void ldsm_x4(uint32_t* r, uint32_t saddr) {
    asm volatile("ldmatrix.sync.aligned.m8n8.x4.shared.b16 {%0,%1,%2,%3}, [%4];"
        : "=r"(r[0]), "=r"(r[1]), "=r"(r[2]), "=r"(r[3]) : "r"(saddr));
}

// ---------------- kernel 0: convert both weight matrices to fp16 --------------
__global__ void cvt_f16_kernel(const float* __restrict__ in1, u16* __restrict__ out1, int n1_4,
                               const float* __restrict__ in2, u16* __restrict__ out2, int n2_4) {
    int i = blockIdx.x * 256 + threadIdx.x;
    if (i < n1_4) {
        float4 v = *(const float4*)(in1 + i*4);
        uint2 o;
        o.x = pack2(v.x, v.y);
        o.y = pack2(v.z, v.w);
        *(uint2*)(out1 + i*4) = o;
    }
    int j = i - n1_4;
    if (j >= 0 && j < n2_4) {
        float4 v = *(const float4*)(in2 + j*4);
        uint2 o;
        o.x = pack2(v.x, v.y);
        o.y = pack2(v.z, v.w);
        *(uint2*)(out2 + j*4) = o;
    }
}

// ---------------- kernel 1: LayerNorm -> fp16 ---------------------------------
__global__ void __launch_bounds__(256) ln_kernel(const float* __restrict__ x,
                                                 const float* __restrict__ w,
                                                 const float* __restrict__ b) {
    int row  = blockIdx.x * 8 + (threadIdx.x >> 5);
    int lane = threadIdx.x & 31;
    const float* xr = x + (size_t)row * DIM;
    float4 v[3];
    float sum = 0.f, sq = 0.f;
#pragma unroll
    for (int j = 0; j < 3; j++) {
        v[j] = *(const float4*)(xr + j*128 + lane*4);
        sum += v[j].x + v[j].y + v[j].z + v[j].w;
        sq  += v[j].x*v[j].x + v[j].y*v[j].y + v[j].z*v[j].z + v[j].w*v[j].w;
    }
#pragma unroll
    for (int o = 16; o; o >>= 1) {
        sum += __shfl_xor_sync(0xffffffffu, sum, o);
        sq  += __shfl_xor_sync(0xffffffffu, sq,  o);
    }
    float mean = sum * (1.f/DIM);
    float var  = sq  * (1.f/DIM) - mean*mean;
    float inv  = rsqrtf(var + 1e-5f);
    u16* orow = g_xn16 + (size_t)row * DIM;
#pragma unroll
    for (int j = 0; j < 3; j++) {
        float4 ww = *(const float4*)(w + j*128 + lane*4);
        float4 bb = *(const float4*)(b + j*128 + lane*4);
        uint2 o4;
        o4.x = pack2((v[j].x - mean)*inv*ww.x + bb.x, (v[j].y - mean)*inv*ww.y + bb.y);
        o4.y = pack2((v[j].z - mean)*inv*ww.z + bb.z, (v[j].w - mean)*inv*ww.w + bb.w);
        *(uint2*)(orow + j*128 + lane*4) = o4;
    }
}

// ---------------- bias expansion: gb16[h][n][m] = bias*log2e, fp16 ------------
__global__ void bias_expand(const float* __restrict__ ab, const int* __restrict__ bidx) {
    int n = blockIdx.x, h = blockIdx.y, m = threadIdx.x;
    float v = -1e30f;                              // -> -inf in fp16 -> ex2 = 0
    if (n < NT && m < NT) v = ab[h*NT + bidx[n*NT + m]] * LOG2E;
    half hv = __float2half_rn(v);
    g_b16[((size_t)h*NP + n)*NP + m] = *(u16*)&hv;
}

// ---------------- kernel 2/4: FP16 GEMM, 128x128, k-slab 64, 2-stage, ldmatrix
// (round-11 structure: measured best — do not touch)
#define GP2 36
#define GSTG (2*128*GP2)   // half2 per stage (A then B)
template<bool QKV>
__global__ void __launch_bounds__(256) gemm_f16(const u16* __restrict__ W,
                                                const float* __restrict__ bias,
                                                float* __restrict__ C) {
    extern __shared__ uint32_t sm[];
    const u16* A = QKV ? g_xn16 : g_att16;

    int tid  = threadIdx.x;
    int wid  = tid >> 5, lane = tid & 31;
    int g = lane >> 2, t = lane & 3;
    int warp_m = (wid >> 1) * 32;   // 0,32,64,96
    int warp_n = (wid & 1) * 64;    // 0,64
    int col0 = blockIdx.x * 128;
    int row0 = blockIdx.y * 128;

    int lr = tid >> 3;              // 0..31
    int lc = tid & 7;               // 16B chunk in a 128B data row
    uint32_t sb = (uint32_t)__cvta_generic_to_shared(sm);

    // ldmatrix lane address components (half2 units)
    int a_row = warp_m + (lane & 15);                       // + mt*16
    int a_off = (lane >> 4) * 4;                            // + kc*8
    int b_row = warp_n + ((lane & 7) | ((lane >> 4) << 3)); // + p*16
    int b_off = ((lane >> 3) & 1) * 4;                      // + kc*8

    float acc[2][8][4];
#pragma unroll
    for (int i = 0; i < 2; i++)
#pragma unroll
        for (int j = 0; j < 8; j++)
#pragma unroll
            for (int k = 0; k < 4; k++) acc[i][j][k] = 0.f;

    auto load_stage = [&](int st, int kt) {
        uint32_t baseA = sb + st*GSTG*4;
        uint32_t baseB = baseA + 128*GP2*4;
#pragma unroll
        for (int it = 0; it < 4; it++) {
            int r = lr + it*32;
            cp_async16(baseA + r*GP2*4 + lc*16,
                       A + (size_t)(row0 + r)*DIM + kt*64 + lc*8);
            cp_async16(baseB + r*GP2*4 + lc*16,
                       W + (size_t)(col0 + r)*DIM + kt*64 + lc*8);
        }
        asm volatile("cp.async.commit_group;\n" ::);
    };

    const int T = DIM / 64;         // 6
    load_stage(0, 0);

    for (int tt = 0; tt < T; tt++) {
        if (tt + 1 < T) {
            load_stage((tt+1)&1, tt+1);
            asm volatile("cp.async.wait_group 1;\n" ::);
        } else {
            asm volatile("cp.async.wait_group 0;\n" ::);
        }
        __syncthreads();
        uint32_t sbA = sb + (tt&1)*GSTG*4;
        uint32_t sbB = sbA + 128*GP2*4;
#pragma unroll
        for (int kc = 0; kc < 4; kc++) {          // 4 x k16 chunks in 64-k slab
            uint32_t af[2][4], bf[8][2];
#pragma unroll
            for (int mt = 0; mt < 2; mt++)
                ldsm_x4(af[mt], sbA + ((a_row + mt*16)*GP2 + kc*8 + a_off)*4);
#pragma unroll
            for (int p = 0; p < 4; p++) {
                uint32_t r4[4];
                ldsm_x4(r4, sbB + ((b_row + p*16)*GP2 + kc*8 + b_off)*4);
                bf[2*p  ][0] = r4[0]; bf[2*p  ][1] = r4[1];
                bf[2*p+1][0] = r4[2]; bf[2*p+1][1] = r4[3];
            }
#pragma unroll
            for (int mt = 0; mt < 2; mt++)
#pragma unroll
                for (int nt = 0; nt < 8; nt++)
                    mma_f16(acc[mt][nt], af[mt], bf[nt]);
        }
        __syncthreads();
    }

#pragma unroll
    for (int mt = 0; mt < 2; mt++) {
#pragma unroll
        for (int nt = 0; nt < 8; nt++) {
            int nn0 = col0 + warp_n + nt*8 + 2*t;
#pragma unroll
            for (int rr = 0; rr < 2; rr++) {
                int m = row0 + warp_m + mt*16 + g + rr*8;
                float v0 = acc[mt][nt][rr*2+0] + bias[nn0];
                float v1 = acc[mt][nt][rr*2+1] + bias[nn0+1];
                if (QKV) {
                    int h  = nn0 / 96, cm = nn0 - h*96;
                    int seg = cm >> 5, c = cm & 31;
                    if (seg == 0) { v0 *= QK_SCALE*LOG2E; v1 *= QK_SCALE*LOG2E; }
                    int b_ = m / NT, n_ = m - b_*NT;
                    u16* dst = (seg == 0 ? g_q16 : (seg == 1 ? g_k16 : g_v16))
                               + ((size_t)(b_*HH + h)*NT + n_)*32 + c;
                    *(uint32_t*)dst = pack2(v0, v1);
                } else {
                    float2 o2 = {v0, v1};
                    *(float2*)(C + (size_t)m*DIM + nn0) = o2;
                }
            }
        }
    }
}

// ---------------- kernel 3: fp16 flash attention (no-max softmax, ex2) --------
// log2e folded into q and bias -> bare ex2.approx in the inner loop.
#define KP2 20
#define VP2 108
template<int NTC>
__device__ __forceinline__ void attn_chunk(int cb, const uint32_t qa[2][4],
                                           const u16* gb0, const u16* gb1,
                                           const uint32_t* Ksh, const uint32_t* Vt,
                                           int lane, float& l0, float& l1, float o[4][4]) {
    int g = lane >> 2, t = lane & 3;
    float s[NTC][4];
#pragma unroll
    for (int nt = 0; nt < NTC; nt++) { s[nt][0]=0.f; s[nt][1]=0.f; s[nt][2]=0.f; s[nt][3]=0.f; }
#pragma unroll
    for (int nt = 0; nt < NTC; nt++) {
        int m = cb + nt*8 + g;
#pragma unroll
        for (int kc = 0; kc < 2; kc++) {
            uint32_t bfr[2];
            bfr[0] = Ksh[m*KP2 + kc*8 + t];
            bfr[1] = Ksh[m*KP2 + kc*8 + t + 4];
            mma_f16(s[nt], qa[kc], bfr);
        }
    }
#pragma unroll
    for (int nt = 0; nt < NTC; nt++) {
        int cc = cb + nt*8 + 2*t;
        float2 b0 = __half22float2(*(const half2*)(gb0 + cc));
        float2 b1 = __half22float2(*(const half2*)(gb1 + cc));
        s[nt][0] = ex2(s[nt][0] + b0.x); l0 += s[nt][0];
        s[nt][1] = ex2(s[nt][1] + b0.y); l0 += s[nt][1];
        s[nt][2] = ex2(s[nt][2] + b1.x); l1 += s[nt][2];
        s[nt][3] = ex2(s[nt][3] + b1.y); l1 += s[nt][3];
    }
    // O += P V : P C-frag (c0,c1)=(tok 2t,2t+1) maps directly to fp16 A-frag
#pragma unroll
    for (int gi = 0; gi < NTC/2; gi++) {
        uint32_t pa[4];
        pa[0] = pack2(s[2*gi  ][0], s[2*gi  ][1]);
        pa[1] = pack2(s[2*gi  ][2], s[2*gi  ][3]);
        pa[2] = pack2(s[2*gi+1][0], s[2*gi+1][1]);
        pa[3] = pack2(s[2*gi+1][2], s[2*gi+1][3]);
        int jb = cb/2 + gi*8 + t;
#pragma unroll
        for (int vt = 0; vt < 4; vt++) {
            int d = vt*8 + g;
            uint32_t bfr[2];
            bfr[0] = Vt[d*VP2 + jb];
            bfr[1] = Vt[d*VP2 + jb + 4];
            mma_f16(o[vt], pa, bfr);
        }
    }
}

__global__ void __launch_bounds__(224, 2) attn_mma() {
    extern __shared__ uint32_t smu[];
    uint32_t* Ksh = smu;                 // [208][20] half2
    uint32_t* Vt  = smu + NP*KP2;        // [32][108] half2, (tok even, tok odd)

    int bh = blockIdx.x;
    int b_ = bh / HH;
    int h  = bh - b_*HH;
    int tid = threadIdx.x, w = tid >> 5, lane = tid & 31;
    int g = lane >> 2, t = lane & 3;

    for (int i = tid; i < NP*4; i += 224) {
        int m = i >> 2, c4 = i & 3;
        uint4 kv = {0u,0u,0u,0u};
        if (m < NT) kv = *(const uint4*)(g_k16 + ((size_t)bh*NT + m)*KD + c4*8);
        *(uint4*)&Ksh[m*KP2 + c4*4] = kv;
    }
    for (int i = tid; i < 104*16; i += 224) {
        int j = i >> 4, d2 = i & 15;
        uint32_t va = 0u, vb = 0u;
        if (2*j < NT) {
            va = *(const uint32_t*)(g_v16 + ((size_t)bh*NT + 2*j  )*VD + d2*2);
            vb = *(const uint32_t*)(g_v16 + ((size_t)bh*NT + 2*j+1)*VD + d2*2);
        }
        half2 ha = *(half2*)&va, hb = *(half2*)&vb;
        half2 lo = __halves2half2(__low2half(ha),  __low2half(hb));
        half2 hi = __halves2half2(__high2half(ha), __high2half(hb));
        Vt[(2*d2  )*VP2 + j] = *(uint32_t*)&lo;
        Vt[(2*d2+1)*VP2 + j] = *(uint32_t*)&hi;
    }
    __syncthreads();

    for (int iter = 0; iter < 2; iter++) {
        int tile = w + iter*7;
        if (tile >= 13) break;
        int r0 = tile*16 + g;
        int r1 = r0 + 8;

        uint32_t qa[2][4];
        const u16* q0p = g_q16 + ((size_t)bh*NT + r0)*KD;
        const u16* q1p = g_q16 + ((size_t)bh*NT + r1)*KD;
#pragma unroll
        for (int kc = 0; kc < 2; kc++) {
            qa[kc][0] = (r0 < NT) ? *(const uint32_t*)(q0p + (kc*8 + t)*2)     : 0u;
            qa[kc][1] = (r1 < NT) ? *(const uint32_t*)(q1p + (kc*8 + t)*2)     : 0u;
            qa[kc][2] = (r0 < NT) ? *(const uint32_t*)(q0p + (kc*8 + t + 4)*2) : 0u;
            qa[kc][3] = (r1 < NT) ? *(const uint32_t*)(q1p + (kc*8 + t + 4)*2) : 0u;
        }

        const u16* gb0 = g_b16 + ((size_t)h*NP + r0)*NP;
        const u16* gb1 = g_b16 + ((size_t)h*NP + r1)*NP;

        float l0 = 0.f, l1 = 0.f;
        float o[4][4];
#pragma unroll
        for (int vt = 0; vt < 4; vt++) { o[vt][0]=0.f; o[vt][1]=0.f; o[vt][2]=0.f; o[vt][3]=0.f; }

        attn_chunk<14>(0,   qa, gb0, gb1, Ksh, Vt, lane, l0, l1, o);   // cols 0..111
        attn_chunk<12>(112, qa, gb0, gb1, Ksh, Vt, lane, l0, l1, o);   // cols 112..207

        l0 += __shfl_xor_sync(0xffffffffu, l0, 1);
        l0 += __shfl_xor_sync(0xffffffffu, l0, 2);
        l1 += __shfl_xor_sync(0xffffffffu, l1, 1);
        l1 += __shfl_xor_sync(0xffffffffu, l1, 2);
        float inv0 = __fdividef(1.f, l0);
        float inv1 = __fdividef(1.f, l1);

        if (r0 < NT) {
            u16* orow = g_att16 + ((size_t)(b_*NT + r0))*DIM + h*VD;
#pragma unroll
            for (int vt = 0; vt < 4; vt++)
                *(uint32_t*)(orow + vt*8 + 2*t) = pack2(o[vt][0]*inv0, o[vt][1]*inv0);
        }
        if (r1 < NT) {
            u16* orow = g_att16 + ((size_t)(b_*NT + r1))*DIM + h*VD;
#pragma unroll
            for (int vt = 0; vt < 4; vt++)
                *(uint32_t*)(orow + vt*8 + 2*t) = pack2(o[vt][2]*inv1, o[vt][3]*inv1);
        }
    }
}

// ---------------- launch ------------------------------------------------------
extern "C" void kernel_launch(void* const* d_in, const int* in_sizes, int n_in,
                              void* d_out, int out_size) {
    const float* x      = (const float*)d_in[0];
    const float* norm_w = (const float*)d_in[1];
    const float* norm_b = (const float*)d_in[2];
    const float* qkv_w  = (const float*)d_in[3];
    const float* qkv_b  = (const float*)d_in[4];
    const float* attb   = (const float*)d_in[5];
    const float* proj_w = (const float*)d_in[6];
    const float* proj_b = (const float*)d_in[7];
    const int*   bidx   = (const int*)  d_in[8];
    float* out = (float*)d_out;

    u16* qkvw16;  cudaGetSymbolAddress((void**)&qkvw16,  g_qkvw16);
    u16* projw16; cudaGetSymbolAddress((void**)&projw16, g_projw16);

    const int gemm_smem = 2 * GSTG * (int)sizeof(uint32_t);               // 73728
    const int attn_smem = (NP*KP2 + 32*VP2) * (int)sizeof(uint32_t);      // 30464
    cudaFuncSetAttribute(gemm_f16<true >, cudaFuncAttributeMaxDynamicSharedMemorySize, gemm_smem);
    cudaFuncSetAttribute(gemm_f16<false>, cudaFuncAttributeMaxDynamicSharedMemorySize, gemm_smem);
    cudaFuncSetAttribute(attn_mma,        cudaFuncAttributeMaxDynamicSharedMemorySize, attn_smem);

    const int ncvt = FF*DIM/4 + DIM*DIM/4;
    cvt_f16_kernel<<<(ncvt + 255)/256, 256>>>(qkv_w, qkvw16, FF*DIM/4,
                                              proj_w, projw16, DIM*DIM/4);
    ln_kernel<<<MM/8, 256>>>(x, norm_w, norm_b);
    bias_expand<<<dim3(NP, HH), NP>>>(attb, bidx);
    gemm_f16<true ><<<dim3(FF/128,  MM/128), 256, gemm_smem>>>(qkvw16, qkv_b, nullptr);
    attn_mma<<<BB*HH, 224, attn_smem>>>();
    gemm_f16<false><<<dim3(DIM/128, MM/128), 256, gemm_smem>>>(projw16, proj_b, out);
}

// round 16
// speedup vs baseline: 1.1050x; 1.0090x over previous
#include <cuda_runtime.h>
#include <cuda_fp16.h>
#include <stdint.h>
#include <math.h>

#define BB   256
#define NT   196
#define NP   208              // NT padded to 13*16
#define DIM  384
#define HH   12
#define KD   32
#define VD   32
#define MM   (BB*NT)          // 50176
#define FF   (HH*(2*KD+VD))   // 1152
#define QK_SCALE 0.17677669529663687f  // 32^-0.5
#define LOG2E    1.4426950408889634f

typedef unsigned short u16;

// ---------------- scratch (static device arrays; no cudaMalloc) ---------------
__device__ u16   g_xn16 [MM*DIM];        // LN output, fp16
__device__ u16   g_q16  [BB*HH*NT*KD];   // q*scale*log2e, fp16
__device__ u16   g_k16  [BB*HH*NT*KD];
__device__ u16   g_v16  [BB*HH*NT*VD];
__device__ u16   g_att16[MM*DIM];        // attention out, fp16
__device__ u16   g_b16  [HH*NP*NP];      // expanded bias*log2e fp16, pad = -inf
__device__ u16   g_qkvw16 [FF*DIM];      // weights, fp16
__device__ u16   g_projw16[DIM*DIM];

// ---------------- helpers -----------------------------------------------------
__device__ __forceinline__ uint32_t pack2(float lo, float hi) {
    half2 h = __floats2half2_rn(lo, hi);
    return *(uint32_t*)&h;
}
__device__ __forceinline__ float ex2(float x) {
    float r;
    asm("ex2.approx.f32 %0, %1;" : "=f"(r) : "f"(x));
    return r;
}
__device__ __forceinline__ void mma_f16(float* c, const uint32_t* a, const uint32_t* b) {
    asm volatile(
        "mma.sync.aligned.m16n8k16.row.col.f32.f16.f16.f32 "
        "{%0,%1,%2,%3}, {%4,%5,%6,%7}, {%8,%9}, {%0,%1,%2,%3};"
        : "+f"(c[0]), "+f"(c[1]), "+f"(c[2]), "+f"(c[3])
        : "r"(a[0]), "r"(a[1]), "r"(a[2]), "r"(a[3]), "r"(b[0]), "r"(b[1]));
}
__device__ __forceinline__ void cp_async16(uint32_t saddr, const void* gptr) {
    asm volatile("cp.async.ca.shared.global [%0], [%1], 16;\n" :: "r"(saddr), "l"(gptr));
}
__device__ __forceinline__ void ldsm_x4(uint32_t* r, uint32_t saddr) {
    asm volatile("ldmatrix.sync.aligned.m8n8.x4.shared.b16 {%0,%1,%2,%3}, [%4];"
        : "=r"(r[0]), "=r"(r[1]), "=r"(r[2]), "=r"(r[3]) : "r"(saddr));
}

// ---------------- kernel 0: fused prep (weight cvt + bias expand) -------------
// blocks [0, NCVT): convert qkv_w then proj_w to fp16
// blocks [NCVT, NCVT+NBIAS): expand attention bias table (fp16, *log2e)
#define N1_4  (FF*DIM/4)         // 110592
#define N2_4  (DIM*DIM/4)        // 36864
#define NCVT  ((N1_4 + N2_4)/256)             // 576
#define NBIAS ((HH*NP*NP)/256)                // 2028 (HH*NP*NP = 519168 = 2028*256)
__global__ void prep_kernel(const float* __restrict__ qkv_w,
                            const float* __restrict__ proj_w,
                            const float* __restrict__ ab,
                            const int* __restrict__ bidx) {
    int bid = blockIdx.x;
    if (bid < NCVT) {
        int i = bid * 256 + threadIdx.x;
        const float* src; u16* dst;
        if (i < N1_4) { src = qkv_w + i*4;          dst = g_qkvw16 + i*4; }
        else          { src = proj_w + (i-N1_4)*4;  dst = g_projw16 + (i-N1_4)*4; }
        float4 v = *(const float4*)src;
        uint2 o;
        o.x = pack2(v.x, v.y);
        o.y = pack2(v.z, v.w);
        *(uint2*)dst = o;
    } else {
        int j = (bid - NCVT) * 256 + threadIdx.x;   // < HH*NP*NP
        int h = j / (NP*NP);
        int rem = j - h*NP*NP;
        int n = rem / NP, m = rem - n*NP;
        float v = -1e30f;                            // -> -inf in fp16 -> ex2 = 0
        if (n < NT && m < NT) v = ab[h*NT + bidx[n*NT + m]] * LOG2E;
        half hv = __float2half_rn(v);
        g_b16[j] = *(u16*)&hv;
    }
}

// ---------------- kernel 1: LayerNorm -> fp16, 2 rows per warp ----------------
__global__ void __launch_bounds__(256) ln_kernel(const float* __restrict__ x,
                                                 const float* __restrict__ w,
                                                 const float* __restrict__ b) {
    int row0 = blockIdx.x * 16 + (threadIdx.x >> 5) * 2;
    int lane = threadIdx.x & 31;
    const float* xr0 = x + (size_t)row0 * DIM;
    const float* xr1 = xr0 + DIM;
    float4 v0[3], v1[3];
    float s0 = 0.f, q0 = 0.f, s1 = 0.f, q1 = 0.f;
#pragma unroll
    for (int j = 0; j < 3; j++) {
        v0[j] = *(const float4*)(xr0 + j*128 + lane*4);
        v1[j] = *(const float4*)(xr1 + j*128 + lane*4);
    }
#pragma unroll
    for (int j = 0; j < 3; j++) {
        s0 += v0[j].x + v0[j].y + v0[j].z + v0[j].w;
        q0 += v0[j].x*v0[j].x + v0[j].y*v0[j].y + v0[j].z*v0[j].z + v0[j].w*v0[j].w;
        s1 += v1[j].x + v1[j].y + v1[j].z + v1[j].w;
        q1 += v1[j].x*v1[j].x + v1[j].y*v1[j].y + v1[j].z*v1[j].z + v1[j].w*v1[j].w;
    }
#pragma unroll
    for (int o = 16; o; o >>= 1) {
        s0 += __shfl_xor_sync(0xffffffffu, s0, o);
        q0 += __shfl_xor_sync(0xffffffffu, q0, o);
        s1 += __shfl_xor_sync(0xffffffffu, s1, o);
        q1 += __shfl_xor_sync(0xffffffffu, q1, o);
    }
    float mean0 = s0 * (1.f/DIM), mean1 = s1 * (1.f/DIM);
    float inv0 = rsqrtf(q0 * (1.f/DIM) - mean0*mean0 + 1e-5f);
    float inv1 = rsqrtf(q1 * (1.f/DIM) - mean1*mean1 + 1e-5f);
    u16* orow0 = g_xn16 + (size_t)row0 * DIM;
    u16* orow1 = orow0 + DIM;
#pragma unroll
    for (int j = 0; j < 3; j++) {
        float4 ww = *(const float4*)(w + j*128 + lane*4);
        float4 bb = *(const float4*)(b + j*128 + lane*4);
        uint2 o4;
        o4.x = pack2((v0[j].x - mean0)*inv0*ww.x + bb.x, (v0[j].y - mean0)*inv0*ww.y + bb.y);
        o4.y = pack2((v0[j].z - mean0)*inv0*ww.z + bb.z, (v0[j].w - mean0)*inv0*ww.w + bb.w);
        *(uint2*)(orow0 + j*128 + lane*4) = o4;
        o4.x = pack2((v1[j].x - mean1)*inv1*ww.x + bb.x, (v1[j].y - mean1)*inv1*ww.y + bb.y);
        o4.y = pack2((v1[j].z - mean1)*inv1*ww.z + bb.z, (v1[j].w - mean1)*inv1*ww.w + bb.w);
        *(uint2*)(orow1 + j*128 + lane*4) = o4;
    }
}

// ---------------- kernel 2/4: FP16 GEMM, 128x128, k-slab 64, 2-stage, ldmatrix
// (round-11 structure: measured best — do not touch)
#define GP2 36
#define GSTG (2*128*GP2)   // half2 per stage (A then B)
template<bool QKV>
__global__ void __launch_bounds__(256) gemm_f16(const u16* __restrict__ W,
                                                const float* __restrict__ bias,
                                                float* __restrict__ C) {
    extern __shared__ uint32_t sm[];
    const u16* A = QKV ? g_xn16 : g_att16;

    int tid  = threadIdx.x;
    int wid  = tid >> 5, lane = tid & 31;
    int g = lane >> 2, t = lane & 3;
    int warp_m = (wid >> 1) * 32;   // 0,32,64,96
    int warp_n = (wid & 1) * 64;    // 0,64
    int col0 = blockIdx.x * 128;
    int row0 = blockIdx.y * 128;

    int lr = tid >> 3;              // 0..31
    int lc = tid & 7;               // 16B chunk in a 128B data row
    uint32_t sb = (uint32_t)__cvta_generic_to_shared(sm);

    // ldmatrix lane address components (half2 units)
    int a_row = warp_m + (lane & 15);                       // + mt*16
    int a_off = (lane >> 4) * 4;                            // + kc*8
    int b_row = warp_n + ((lane & 7) | ((lane >> 4) << 3)); // + p*16
    int b_off = ((lane >> 3) & 1) * 4;                      // + kc*8

    float acc[2][8][4];
#pragma unroll
    for (int i = 0; i < 2; i++)
#pragma unroll
        for (int j = 0; j < 8; j++)
#pragma unroll
            for (int k = 0; k < 4; k++) acc[i][j][k] = 0.f;

    auto load_stage = [&](int st, int kt) {
        uint32_t baseA = sb + st*GSTG*4;
        uint32_t baseB = baseA + 128*GP2*4;
#pragma unroll
        for (int it = 0; it < 4; it++) {
            int r = lr + it*32;
            cp_async16(baseA + r*GP2*4 + lc*16,
                       A + (size_t)(row0 + r)*DIM + kt*64 + lc*8);
            cp_async16(baseB + r*GP2*4 + lc*16,
                       W + (size_t)(col0 + r)*DIM + kt*64 + lc*8);
        }
        asm volatile("cp.async.commit_group;\n" ::);
    };

    const int T = DIM / 64;         // 6
    load_stage(0, 0);

    for (int tt = 0; tt < T; tt++) {
        if (tt + 1 < T) {
            load_stage((tt+1)&1, tt+1);
            asm volatile("cp.async.wait_group 1;\n" ::);
        } else {
            asm volatile("cp.async.wait_group 0;\n" ::);
        }
        __syncthreads();
        uint32_t sbA = sb + (tt&1)*GSTG*4;
        uint32_t sbB = sbA + 128*GP2*4;
#pragma unroll
        for (int kc = 0; kc < 4; kc++) {          // 4 x k16 chunks in 64-k slab
            uint32_t af[2][4], bf[8][2];
#pragma unroll
            for (int mt = 0; mt < 2; mt++)
                ldsm_x4(af[mt], sbA + ((a_row + mt*16)*GP2 + kc*8 + a_off)*4);
#pragma unroll
            for (int p = 0; p < 4; p++) {
                uint32_t r4[4];
                ldsm_x4(r4, sbB + ((b_row + p*16)*GP2 + kc*8 + b_off)*4);
                bf[2*p  ][0] = r4[0]; bf[2*p  ][1] = r4[1];
                bf[2*p+1][0] = r4[2]; bf[2*p+1][1] = r4[3];
            }
#pragma unroll
            for (int mt = 0; mt < 2; mt++)
#pragma unroll
                for (int nt = 0; nt < 8; nt++)
                    mma_f16(acc[mt][nt], af[mt], bf[nt]);
        }
        __syncthreads();
    }

#pragma unroll
    for (int mt = 0; mt < 2; mt++) {
#pragma unroll
        for (int nt = 0; nt < 8; nt++) {
            int nn0 = col0 + warp_n + nt*8 + 2*t;
#pragma unroll
            for (int rr = 0; rr < 2; rr++) {
                int m = row0 + warp_m + mt*16 + g + rr*8;
                float v0 = acc[mt][nt][rr*2+0] + bias[nn0];
                float v1 = acc[mt][nt][rr*2+1] + bias[nn0+1];
                if (QKV) {
                    int h  = nn0 / 96, cm = nn0 - h*96;
                    int seg = cm >> 5, c = cm & 31;
                    if (seg == 0) { v0 *= QK_SCALE*LOG2E; v1 *= QK_SCALE*LOG2E; }
                    int b_ = m / NT, n_ = m - b_*NT;
                    u16* dst = (seg == 0 ? g_q16 : (seg == 1 ? g_k16 : g_v16))
                               + ((size_t)(b_*HH + h)*NT + n_)*32 + c;
                    *(uint32_t*)dst = pack2(v0, v1);
                } else {
                    float2 o2 = {v0, v1};
                    *(float2*)(C + (size_t)m*DIM + nn0) = o2;
                }
            }
        }
    }
}

// ---------------- kernel 3: fp16 flash attention (no-max softmax, ex2) --------
#define KP2 20
#define VP2 108
template<int NTC>
__device__ __forceinline__ void attn_chunk(int cb, const uint32_t qa[2][4],
                                           const u16* gb0, const u16* gb1,
                                           const uint32_t* Ksh, const uint32_t* Vt,
                                           int lane, float& l0, float& l1, float o[4][4]) {
    int g = lane >> 2, t = lane & 3;
    float s[NTC][4];
#pragma unroll
    for (int nt = 0; nt < NTC; nt++) { s[nt][0]=0.f; s[nt][1]=0.f; s[nt][2]=0.f; s[nt][3]=0.f; }
#pragma unroll
    for (int nt = 0; nt < NTC; nt++) {
        int m = cb + nt*8 + g;
#pragma unroll
        for (int kc = 0; kc < 2; kc++) {
            uint32_t bfr[2];
            bfr[0] = Ksh[m*KP2 + kc*8 + t];
            bfr[1] = Ksh[m*KP2 + kc*8 + t + 4];
            mma_f16(s[nt], qa[kc], bfr);
        }
    }
#pragma unroll
    for (int nt = 0; nt < NTC; nt++) {
        int cc = cb + nt*8 + 2*t;
        float2 b0 = __half22float2(*(const half2*)(gb0 + cc));
        float2 b1 = __half22float2(*(const half2*)(gb1 + cc));
        s[nt][0] = ex2(s[nt][0] + b0.x); l0 += s[nt][0];
        s[nt][1] = ex2(s[nt][1] + b0.y); l0 += s[nt][1];
        s[nt][2] = ex2(s[nt][2] + b1.x); l1 += s[nt][2];
        s[nt][3] = ex2(s[nt][3] + b1.y); l1 += s[nt][3];
    }
    // O += P V : P C-frag (c0,c1)=(tok 2t,2t+1) maps directly to fp16 A-frag
#pragma unroll
    for (int gi = 0; gi < NTC/2; gi++) {
        uint32_t pa[4];
        pa[0] = pack2(s[2*gi  ][0], s[2*gi  ][1]);
        pa[1] = pack2(s[2*gi  ][2], s[2*gi  ][3]);
        pa[2] = pack2(s[2*gi+1][0], s[2*gi+1][1]);
        pa[3] = pack2(s[2*gi+1][2], s[2*gi+1][3]);
        int jb = cb/2 + gi*8 + t;
#pragma unroll
        for (int vt = 0; vt < 4; vt++) {
            int d = vt*8 + g;
            uint32_t bfr[2];
            bfr[0] = Vt[d*VP2 + jb];
            bfr[1] = Vt[d*VP2 + jb + 4];
            mma_f16(o[vt], pa, bfr);
        }
    }
}

__global__ void __launch_bounds__(224, 2) attn_mma() {
    extern __shared__ uint32_t smu[];
    uint32_t* Ksh = smu;                 // [208][20] half2
    uint32_t* Vt  = smu + NP*KP2;        // [32][108] half2, (tok even, tok odd)

    int bh = blockIdx.x;
    int b_ = bh / HH;
    int h  = bh - b_*HH;
    int tid = threadIdx.x, w = tid >> 5, lane = tid & 31;
    int g = lane >> 2, t = lane & 3;

    for (int i = tid; i < NP*4; i += 224) {
        int m = i >> 2, c4 = i & 3;
        uint4 kv = {0u,0u,0u,0u};
        if (m < NT) kv = *(const uint4*)(g_k16 + ((size_t)bh*NT + m)*KD + c4*8);
        *(uint4*)&Ksh[m*KP2 + c4*4] = kv;
    }
    for (int i = tid; i < 104*16; i += 224) {
        int j = i >> 4, d2 = i & 15;
        uint32_t va = 0u, vb = 0u;
        if (2*j < NT) {
            va = *(const uint32_t*)(g_v16 + ((size_t)bh*NT + 2*j  )*VD + d2*2);
            vb = *(const uint32_t*)(g_v16 + ((size_t)bh*NT + 2*j+1)*VD + d2*2);
        }
        half2 ha = *(half2*)&va, hb = *(half2*)&vb;
        half2 lo = __halves2half2(__low2half(ha),  __low2half(hb));
        half2 hi = __halves2half2(__high2half(ha), __high2half(hb));
        Vt[(2*d2  )*VP2 + j] = *(uint32_t*)&lo;
        Vt[(2*d2+1)*VP2 + j] = *(uint32_t*)&hi;
    }
    __syncthreads();

    for (int iter = 0; iter < 2; iter++) {
        int tile = w + iter*7;
        if (tile >= 13) break;
        int r0 = tile*16 + g;
        int r1 = r0 + 8;

        uint32_t qa[2][4];
        const u16* q0p = g_q16 + ((size_t)bh*NT + r0)*KD;
        const u16* q1p = g_q16 + ((size_t)bh*NT + r1)*KD;
#pragma unroll
        for (int kc = 0; kc < 2; kc++) {
            qa[kc][0] = (r0 < NT) ? *(const uint32_t*)(q0p + (kc*8 + t)*2)     : 0u;
            qa[kc][1] = (r1 < NT) ? *(const uint32_t*)(q1p + (kc*8 + t)*2)     : 0u;
            qa[kc][2] = (r0 < NT) ? *(const uint32_t*)(q0p + (kc*8 + t + 4)*2) : 0u;
            qa[kc][3] = (r1 < NT) ? *(const uint32_t*)(q1p + (kc*8 + t + 4)*2) : 0u;
        }

        const u16* gb0 = g_b16 + ((size_t)h*NP + r0)*NP;
        const u16* gb1 = g_b16 + ((size_t)h*NP + r1)*NP;

        float l0 = 0.f, l1 = 0.f;
        float o[4][4];
#pragma unroll
        for (int vt = 0; vt < 4; vt++) { o[vt][0]=0.f; o[vt][1]=0.f; o[vt][2]=0.f; o[vt][3]=0.f; }

        attn_chunk<14>(0,   qa, gb0, gb1, Ksh, Vt, lane, l0, l1, o);   // cols 0..111
        attn_chunk<12>(112, qa, gb0, gb1, Ksh, Vt, lane, l0, l1, o);   // cols 112..207

        l0 += __shfl_xor_sync(0xffffffffu, l0, 1);
        l0 += __shfl_xor_sync(0xffffffffu, l0, 2);
        l1 += __shfl_xor_sync(0xffffffffu, l1, 1);
        l1 += __shfl_xor_sync(0xffffffffu, l1, 2);
        float inv0 = __fdividef(1.f, l0);
        float inv1 = __fdividef(1.f, l1);

        if (r0 < NT) {
            u16* orow = g_att16 + ((size_t)(b_*NT + r0))*DIM + h*VD;
#pragma unroll
            for (int vt = 0; vt < 4; vt++)
                *(uint32_t*)(orow + vt*8 + 2*t) = pack2(o[vt][0]*inv0, o[vt][1]*inv0);
        }
        if (r1 < NT) {
            u16* orow = g_att16 + ((size_t)(b_*NT + r1))*DIM + h*VD;
#pragma unroll
            for (int vt = 0; vt < 4; vt++)
                *(uint32_t*)(orow + vt*8 + 2*t) = pack2(o[vt][2]*inv1, o[vt][3]*inv1);
        }
    }
}

// ---------------- launch ------------------------------------------------------
extern "C" void kernel_launch(void* const* d_in, const int* in_sizes, int n_in,
                              void* d_out, int out_size) {
    const float* x      = (const float*)d_in[0];
    const float* norm_w = (const float*)d_in[1];
    const float* norm_b = (const float*)d_in[2];
    const float* qkv_w  = (const float*)d_in[3];
    const float* qkv_b  = (const float*)d_in[4];
    const float* attb   = (const float*)d_in[5];
    const float* proj_w = (const float*)d_in[6];
    const float* proj_b = (const float*)d_in[7];
    const int*   bidx   = (const int*)  d_in[8];
    float* out = (float*)d_out;

    u16* qkvw16;  cudaGetSymbolAddress((void**)&qkvw16,  g_qkvw16);
    u16* projw16; cudaGetSymbolAddress((void**)&projw16, g_projw16);

    const int gemm_smem = 2 * GSTG * (int)sizeof(uint32_t);               // 73728
    const int attn_smem = (NP*KP2 + 32*VP2) * (int)sizeof(uint32_t);      // 30464
    cudaFuncSetAttribute(gemm_f16<true >, cudaFuncAttributeMaxDynamicSharedMemorySize, gemm_smem);
    cudaFuncSetAttribute(gemm_f16<false>, cudaFuncAttributeMaxDynamicSharedMemorySize, gemm_smem);
    cudaFuncSetAttribute(attn_mma,        cudaFuncAttributeMaxDynamicSharedMemorySize, attn_smem);

    prep_kernel<<<NCVT + NBIAS, 256>>>(qkv_w, proj_w, attb, bidx);
    ln_kernel<<<MM/16, 256>>>(x, norm_w, norm_b);
    gemm_f16<true ><<<dim3(FF/128,  MM/128), 256, gemm_smem>>>(qkvw16, qkv_b, nullptr);
    attn_mma<<<BB*HH, 224, attn_smem>>>();
    gemm_f16<false><<<dim3(DIM/128, MM/128), 256, gemm_smem>>>(projw16, proj_b, out);
}